// round 3
// baseline (speedup 1.0000x reference)
#include <cuda_runtime.h>
#include <cuda_bf16.h>

#define ULL unsigned long long

// ---------------- scratch (device globals; no allocation allowed) ----------------
__device__ __align__(256) float g_w0T[1600 * 128];   // [k][o]
__device__ __align__(256) float g_w1T[2560 * 128];   // [k][o]
__device__ __align__(256) float g_h0[16384 * 256];
__device__ __align__(256) float g_h1[16384 * 128];

// ---------------- f32x2 helpers ----------------
__device__ __forceinline__ ULL pk2(float lo, float hi) {
    ULL r; asm("mov.b64 %0, {%1,%2};" : "=l"(r) : "f"(lo), "f"(hi)); return r;
}
__device__ __forceinline__ void upk2(ULL v, float& lo, float& hi) {
    asm("mov.b64 {%0,%1}, %2;" : "=f"(lo), "=f"(hi) : "l"(v));
}
__device__ __forceinline__ ULL mul2(ULL a, ULL b) {
    ULL r; asm("mul.rn.f32x2 %0,%1,%2;" : "=l"(r) : "l"(a), "l"(b)); return r;
}
__device__ __forceinline__ ULL fma2(ULL a, ULL b, ULL c) {
    ULL r; asm("fma.rn.f32x2 %0,%1,%2,%3;" : "=l"(r) : "l"(a), "l"(b), "l"(c)); return r;
}

// ---------------- cp.async helpers ----------------
__device__ __forceinline__ void cpasync16(void* smem, const void* g) {
    unsigned s = (unsigned)__cvta_generic_to_shared(smem);
    asm volatile("cp.async.cg.shared.global [%0], [%1], 16;" :: "r"(s), "l"(g));
}
__device__ __forceinline__ void cpcommit() {
    asm volatile("cp.async.commit_group;" ::: "memory");
}
template<int W> __device__ __forceinline__ void cpwait() {
    asm volatile("cp.async.wait_group %0;" :: "n"(W) : "memory");
}

template<int NV4>
__device__ __forceinline__ void issue_w(float* dst, const float* src, int tid) {
#pragma unroll
    for (int t = 0; t < NV4; t++) {
        int idx = tid + 256 * t;
        cpasync16(dst + idx * 4, src + idx * 4);
    }
    cpcommit();
}

// ---------------- prep: transpose conv weights to [k][o] ----------------
__global__ void prep_kernel(const float* __restrict__ w0, const float* __restrict__ w1) {
    int stride = gridDim.x * blockDim.x;
    int i0 = blockIdx.x * blockDim.x + threadIdx.x;
    for (int idx = i0; idx < 128 * 1600; idx += stride) {
        int o = idx / 1600, k = idx % 1600;
        g_w0T[k * 128 + o] = w0[idx];
    }
    for (int idx = i0; idx < 128 * 2560; idx += stride) {
        int o = idx / 2560, k = idx % 2560;
        g_w1T[k * 128 + o] = w1[idx];
    }
}

// ---------------- CIN chunk compute ----------------
// wb: smem weight chunk [LEN][128]; xm: packed x0[m][2dp..] per batch;
// xn0: base of xn source (batch stride xstr floats, row stride 32 floats)
template<int LEN>
__device__ __forceinline__ void chunk_mm(const float* wb, const ULL* xm,
                                         const float* xn0, int xstr,
                                         int dp, int og, ULL acc[4][8]) {
#pragma unroll 4
    for (int j = 0; j < LEN; j++) {
        const float4 wa = *(const float4*)(wb + j * 128 + og * 8);
        const float4 wc = *(const float4*)(wb + j * 128 + og * 8 + 4);
        ULL wp[8];
        wp[0] = pk2(wa.x, wa.x); wp[1] = pk2(wa.y, wa.y);
        wp[2] = pk2(wa.z, wa.z); wp[3] = pk2(wa.w, wa.w);
        wp[4] = pk2(wc.x, wc.x); wp[5] = pk2(wc.y, wc.y);
        wp[6] = pk2(wc.z, wc.z); wp[7] = pk2(wc.w, wc.w);
#pragma unroll
        for (int b = 0; b < 4; b++) {
            ULL xn = *(const ULL*)(xn0 + b * xstr + j * 32 + dp * 2);
            ULL z = mul2(xm[b], xn);
#pragma unroll
            for (int i = 0; i < 8; i++) acc[b][i] = fma2(wp[i], z, acc[b][i]);
        }
    }
}

// ---------------- CIN + aux kernel: 1 CTA = 4 batches ----------------
// smem layout (floats): s_x[4][40][32]=5120 | s_h1[4][64][32]=8192 |
//                       s_w 2*5120=10240 | s_cin[4][192]=768 | s_aux[4]
__global__ __launch_bounds__(256, 2)
void cin_kernel(const float* __restrict__ x, const float* __restrict__ emb,
                const float* __restrict__ lin_w, const float* __restrict__ lin_b,
                const float* __restrict__ b0c, const float* __restrict__ b1c,
                const float* __restrict__ cow, const float* __restrict__ cob,
                float* __restrict__ out_aux) {
    extern __shared__ float sm[];
    float* s_x   = sm;
    float* s_h1  = sm + 5120;
    float* s_w   = sm + 13312;
    float* s_cin = sm + 23552;
    float* s_aux = sm + 24320;

    int tid = threadIdx.x;
    int b0i = blockIdx.x * 4;
    if (tid < 4) s_aux[tid] = 0.0f;

    // load emb tiles for 4 batches (4*1280 floats, contiguous)
    {
        const float4* esrc = (const float4*)(emb + (size_t)b0i * 1280);
        float4* sxv = (float4*)s_x;
#pragma unroll
        for (int t = 0; t < 5; t++) sxv[tid + 256 * t] = esrc[tid + 256 * t];
    }
    __syncthreads();

    int dp = tid & 15;       // d-pair 0..15  (d = 2dp, 2dp+1)
    int og = tid >> 4;       // o-group 0..15 (o = og*8 + i)
    int lane = tid & 31;

    ULL acc[4][8];

    // ================= layer 0: K = 40*40, chunk = one m-row (40 n) =================
#pragma unroll
    for (int b = 0; b < 4; b++)
#pragma unroll
        for (int i = 0; i < 8; i++) acc[b][i] = 0ull;

    issue_w<5>(s_w, g_w0T, tid);
    for (int c = 0; c < 40; c++) {
        const float* wb = s_w + (c & 1) * 5120;
        if (c + 1 < 40) { issue_w<5>(s_w + ((c + 1) & 1) * 5120, g_w0T + (c + 1) * 5120, tid); cpwait<1>(); }
        else cpwait<0>();
        __syncthreads();
        ULL xm[4];
#pragma unroll
        for (int b = 0; b < 4; b++) xm[b] = *(const ULL*)(s_x + b * 1280 + c * 32 + dp * 2);
        chunk_mm<40>(wb, xm, s_x, 1280, dp, og, acc);
        __syncthreads();
    }

    // epilogue 0: bias+relu; og<8 -> h1 to smem; og>=8 -> d-sum -> cin_feat[0..63]
    {
        int o = og * 8;
        float bv[8];
#pragma unroll
        for (int i = 0; i < 8; i++) bv[i] = b0c[o + i];
#pragma unroll
        for (int b = 0; b < 4; b++) {
#pragma unroll
            for (int i = 0; i < 8; i++) {
                float lo, hi; upk2(acc[b][i], lo, hi);
                lo = fmaxf(lo + bv[i], 0.0f);
                hi = fmaxf(hi + bv[i], 0.0f);
                if (og < 8) {
                    float2 v2 = make_float2(lo, hi);
                    *(float2*)(s_h1 + b * 2048 + (o + i) * 32 + dp * 2) = v2;
                } else {
                    float v = lo + hi;
#pragma unroll
                    for (int off = 8; off > 0; off >>= 1)
                        v += __shfl_down_sync(0xffffffffu, v, off, 16);
                    if ((lane & 15) == 0) s_cin[b * 192 + (o + i - 64)] = v;
                }
            }
        }
    }
    __syncthreads();

    // ================= layer 1: K = 40*64, chunk = 32 n (2 chunks per m) =================
#pragma unroll
    for (int b = 0; b < 4; b++)
#pragma unroll
        for (int i = 0; i < 8; i++) acc[b][i] = 0ull;

    issue_w<4>(s_w, g_w1T, tid);
    for (int c = 0; c < 80; c++) {
        const float* wb = s_w + (c & 1) * 5120;
        if (c + 1 < 80) { issue_w<4>(s_w + ((c + 1) & 1) * 5120, g_w1T + (size_t)(c + 1) * 4096, tid); cpwait<1>(); }
        else cpwait<0>();
        __syncthreads();
        int m = c >> 1;
        ULL xm[4];
#pragma unroll
        for (int b = 0; b < 4; b++) xm[b] = *(const ULL*)(s_x + b * 1280 + m * 32 + dp * 2);
        chunk_mm<32>(wb, xm, s_h1 + (c & 1) * 1024, 2048, dp, og, acc);
        __syncthreads();
    }

    // epilogue 1: bias+relu -> d-sum -> cin_feat[64..191]
    {
        int o = og * 8;
        float bv[8];
#pragma unroll
        for (int i = 0; i < 8; i++) bv[i] = b1c[o + i];
#pragma unroll
        for (int b = 0; b < 4; b++) {
#pragma unroll
            for (int i = 0; i < 8; i++) {
                float lo, hi; upk2(acc[b][i], lo, hi);
                lo = fmaxf(lo + bv[i], 0.0f);
                hi = fmaxf(hi + bv[i], 0.0f);
                float v = lo + hi;
#pragma unroll
                for (int off = 8; off > 0; off >>= 1)
                    v += __shfl_down_sync(0xffffffffu, v, off, 16);
                if ((lane & 15) == 0) s_cin[b * 192 + 64 + o + i] = v;
            }
        }
    }
    __syncthreads();

    // ================= aux: x . lin_w + cin_feat . cin_out_w =================
    {
        int b = tid >> 6;      // 0..3
        int j = tid & 63;
        const float* xr = x + (size_t)(b0i + b) * 1280;
        float v = 0.0f;
#pragma unroll 5
        for (int t = 0; t < 20; t++) v += xr[j + 64 * t] * lin_w[j + 64 * t];
#pragma unroll
        for (int t = 0; t < 3; t++) v += s_cin[b * 192 + j + 64 * t] * cow[j + 64 * t];
#pragma unroll
        for (int off = 16; off > 0; off >>= 1)
            v += __shfl_down_sync(0xffffffffu, v, off);
        if (lane == 0) atomicAdd(&s_aux[b], v);
    }
    __syncthreads();
    if (tid < 4) out_aux[b0i + tid] = s_aux[tid] + lin_b[0] + cob[0];
}

// ---------------- deep tower: C = relu(LN(A @ W^T + b)), CTA = 64 rows ----------------
template<int N>
__global__ __launch_bounds__(256, 2)
void deep_kernel(const float* __restrict__ A, int K,
                 const float* __restrict__ W, const float* __restrict__ bias,
                 const float* __restrict__ gam, const float* __restrict__ bet,
                 float* __restrict__ out) {
    constexpr int CPT = N / 32;
    __shared__ float sA[16][64];
    __shared__ float sW[16][N];
    int tid = threadIdx.x;
    int ty = tid >> 5, tx = tid & 31;
    int row0 = blockIdx.x * 64;

    float acc[8][CPT];
#pragma unroll
    for (int q = 0; q < 8; q++)
#pragma unroll
        for (int p = 0; p < CPT; p++) acc[q][p] = 0.0f;

    for (int kt = 0; kt < K; kt += 16) {
        {
            int r = tid >> 2, c = tid & 3;
            float4 a = *(const float4*)(A + (size_t)(row0 + r) * K + kt + c * 4);
            sA[c * 4 + 0][r] = a.x; sA[c * 4 + 1][r] = a.y;
            sA[c * 4 + 2][r] = a.z; sA[c * 4 + 3][r] = a.w;
        }
#pragma unroll
        for (int t = 0; t < N / 64; t++) {
            int v = tid + 256 * t;
            int n = v >> 2, c = v & 3;
            float4 w = *(const float4*)(W + (size_t)n * K + kt + c * 4);
            sW[c * 4 + 0][n] = w.x; sW[c * 4 + 1][n] = w.y;
            sW[c * 4 + 2][n] = w.z; sW[c * 4 + 3][n] = w.w;
        }
        __syncthreads();
#pragma unroll
        for (int k = 0; k < 16; k++) {
            float ra[8], rw[CPT];
#pragma unroll
            for (int q = 0; q < 8; q++) ra[q] = sA[k][ty * 8 + q];
#pragma unroll
            for (int p = 0; p < CPT; p++) rw[p] = sW[k][tx * CPT + p];
#pragma unroll
            for (int q = 0; q < 8; q++)
#pragma unroll
                for (int p = 0; p < CPT; p++) acc[q][p] += ra[q] * rw[p];
        }
        __syncthreads();
    }

    float g[CPT], be[CPT], bv[CPT];
#pragma unroll
    for (int p = 0; p < CPT; p++) {
        g[p] = gam[tx * CPT + p]; be[p] = bet[tx * CPT + p]; bv[p] = bias[tx * CPT + p];
    }
#pragma unroll
    for (int q = 0; q < 8; q++) {
#pragma unroll
        for (int p = 0; p < CPT; p++) acc[q][p] += bv[p];
        float s = 0.0f;
#pragma unroll
        for (int p = 0; p < CPT; p++) s += acc[q][p];
#pragma unroll
        for (int off = 16; off > 0; off >>= 1) s += __shfl_xor_sync(0xffffffffu, s, off);
        float mu = s * (1.0f / N);
        float vs = 0.0f;
#pragma unroll
        for (int p = 0; p < CPT; p++) { float d = acc[q][p] - mu; vs += d * d; }
#pragma unroll
        for (int off = 16; off > 0; off >>= 1) vs += __shfl_xor_sync(0xffffffffu, vs, off);
        float rstd = rsqrtf(vs * (1.0f / N) + 1e-5f);
        size_t row = row0 + ty * 8 + q;
#pragma unroll
        for (int p = 0; p < CPT; p++) {
            float val = (acc[q][p] - mu) * rstd * g[p] + be[p];
            out[row * N + tx * CPT + p] = fmaxf(val, 0.0f);
        }
    }
}

// ---------------- launcher ----------------
extern "C" void kernel_launch(void* const* d_in, const int* in_sizes, int n_in,
                              void* d_out, int out_size) {
    const float* x     = (const float*)d_in[0];
    const float* emb   = (const float*)d_in[1];
    const float* lin_w = (const float*)d_in[2];
    const float* lin_b = (const float*)d_in[3];
    const float* w0    = (const float*)d_in[4];
    const float* b0c   = (const float*)d_in[5];
    const float* w1    = (const float*)d_in[6];
    const float* b1c   = (const float*)d_in[7];
    const float* cow   = (const float*)d_in[8];
    const float* cob   = (const float*)d_in[9];
    const float* dw0   = (const float*)d_in[10];
    const float* db0   = (const float*)d_in[11];
    const float* g0    = (const float*)d_in[12];
    const float* be0   = (const float*)d_in[13];
    const float* dw1   = (const float*)d_in[14];
    const float* db1   = (const float*)d_in[15];
    const float* g1    = (const float*)d_in[16];
    const float* be1   = (const float*)d_in[17];
    const float* dw2   = (const float*)d_in[18];
    const float* db2   = (const float*)d_in[19];
    const float* g2    = (const float*)d_in[20];
    const float* be2   = (const float*)d_in[21];

    float* out = (float*)d_out;
    float* h_out = out;                      // [B,64]
    float* aux_out = out + 16384 * 64;       // [B]

    void* h0p = nullptr; void* h1p = nullptr;
    cudaGetSymbolAddress(&h0p, g_h0);
    cudaGetSymbolAddress(&h1p, g_h1);

    static const int CIN_SMEM = 24324 * 4;
    cudaFuncSetAttribute(cin_kernel, cudaFuncAttributeMaxDynamicSharedMemorySize, CIN_SMEM);

    prep_kernel<<<256, 256>>>(w0, w1);
    cin_kernel<<<4096, 256, CIN_SMEM>>>(x, emb, lin_w, lin_b, b0c, b1c, cow, cob, aux_out);
    deep_kernel<256><<<256, 256>>>(x, 1280, dw0, db0, g0, be0, (float*)h0p);
    deep_kernel<128><<<256, 256>>>((const float*)h0p, 256, dw1, db1, g1, be1, (float*)h1p);
    deep_kernel<64><<<256, 256>>>((const float*)h1p, 128, dw2, db2, g2, be2, h_out);
}

// round 6
// speedup vs baseline: 3.3567x; 3.3567x over previous
#include <cuda_runtime.h>
#include <cuda_bf16.h>

// ---------------- scratch (device globals; no allocation allowed) ----------------
__device__ __align__(256) float g_w0P[200 * 1024];   // layer0 weights, fragment-permuted
__device__ __align__(256) float g_w1P[320 * 1024];   // layer1 weights, fragment-permuted
__device__ __align__(256) float g_h0[16384 * 256];
__device__ __align__(256) float g_h1[16384 * 128];

// ---------------- helpers ----------------
__device__ __forceinline__ unsigned cvt_tf32(float x) {
    unsigned r; asm("cvt.rna.tf32.f32 %0, %1;" : "=r"(r) : "f"(x)); return r;
}

__device__ __forceinline__ void mma8(float c[4], const unsigned a[4], unsigned b0, unsigned b1) {
    asm volatile(
        "mma.sync.aligned.m16n8k8.row.col.f32.tf32.tf32.f32 "
        "{%0,%1,%2,%3}, {%4,%5,%6,%7}, {%8,%9}, {%0,%1,%2,%3};\n"
        : "+f"(c[0]), "+f"(c[1]), "+f"(c[2]), "+f"(c[3])
        : "r"(a[0]), "r"(a[1]), "r"(a[2]), "r"(a[3]), "r"(b0), "r"(b1));
}

__device__ __forceinline__ void cpasync16(void* smem, const void* g) {
    unsigned s = (unsigned)__cvta_generic_to_shared(smem);
    asm volatile("cp.async.cg.shared.global [%0], [%1], 16;" :: "r"(s), "l"(g));
}
__device__ __forceinline__ void cpcommit() {
    asm volatile("cp.async.commit_group;" ::: "memory");
}
template<int W> __device__ __forceinline__ void cpwait() {
    asm volatile("cp.async.wait_group %0;" :: "n"(W) : "memory");
}

// one granule = 4 chunks = 4096 floats = 16KB
__device__ __forceinline__ void issue_gran(float* dst, const float* src, int tid) {
#pragma unroll
    for (int t = 0; t < 4; t++) {
        int idx = (tid + 256 * t) * 4;
        cpasync16(dst + idx, src + idx);
    }
    cpcommit();
}

// ---------------- prep: permute conv weights into B-fragment order (tf32-rounded) ----------------
// layout: [chunk][group g 0..15][lane 0..31][j 0..1]
//   value = W[o = g*8 + (lane>>2)][k = chunk*8 + (lane&3) + j*4]
__global__ void prep_kernel(const float* __restrict__ w0, const float* __restrict__ w1) {
    int stride = gridDim.x * blockDim.x;
    int i0 = blockIdx.x * blockDim.x + threadIdx.x;
    for (int idx = i0; idx < 200 * 1024; idx += stride) {
        int j = idx & 1, lane = (idx >> 1) & 31, g = (idx >> 6) & 15, c = idx >> 10;
        int o = g * 8 + (lane >> 2);
        int k = c * 8 + (lane & 3) + j * 4;
        unsigned v = cvt_tf32(w0[o * 1600 + k]);
        g_w0P[idx] = __uint_as_float(v);
    }
    for (int idx = i0; idx < 320 * 1024; idx += stride) {
        int j = idx & 1, lane = (idx >> 1) & 31, g = (idx >> 6) & 15, c = idx >> 10;
        int o = g * 8 + (lane >> 2);
        int k = c * 8 + (lane & 3) + j * 4;
        unsigned v = cvt_tf32(w1[o * 2560 + k]);
        g_w1P[idx] = __uint_as_float(v);
    }
}

// ---------------- per-chunk MMA: build A on the fly, 16 col-groups x 2 row-tiles ----------------
// xm_base: s_x batch tile [d][44] (x0, row index m)
// xn_base: [d][XNSTR] source of the n-side (x0 stride 44 or h1 stride 68)
template<int XNSTR>
__device__ __forceinline__ void chunk_mma(const float* __restrict__ wb,
                                          const float* __restrict__ xm_base,
                                          const float* __restrict__ xn_base,
                                          int m, int n0, int lane,
                                          float (&acc0)[16][4], float (&acc1)[16][4]) {
    int q = lane >> 2;          // 0..7
    int kc = lane & 3;          // 0..3
    float xmA = xm_base[q * 44 + m];
    float xmB = xm_base[(q + 8) * 44 + m];
    float xmC = xm_base[(q + 16) * 44 + m];
    float xmD = xm_base[(q + 24) * 44 + m];
    const float* xn = xn_base + n0 + kc;
    float xnA0 = xn[q * XNSTR],        xnA4 = xn[q * XNSTR + 4];
    float xnB0 = xn[(q + 8) * XNSTR],  xnB4 = xn[(q + 8) * XNSTR + 4];
    float xnC0 = xn[(q + 16) * XNSTR], xnC4 = xn[(q + 16) * XNSTR + 4];
    float xnD0 = xn[(q + 24) * XNSTR], xnD4 = xn[(q + 24) * XNSTR + 4];

    unsigned a0[4], a1[4];
    a0[0] = cvt_tf32(xmA * xnA0); a0[1] = cvt_tf32(xmB * xnB0);
    a0[2] = cvt_tf32(xmA * xnA4); a0[3] = cvt_tf32(xmB * xnB4);
    a1[0] = cvt_tf32(xmC * xnC0); a1[1] = cvt_tf32(xmD * xnD0);
    a1[2] = cvt_tf32(xmC * xnC4); a1[3] = cvt_tf32(xmD * xnD4);

#pragma unroll
    for (int g = 0; g < 16; g++) {
        float2 b = *(const float2*)(wb + g * 64 + lane * 2);
        unsigned b0 = __float_as_uint(b.x), b1 = __float_as_uint(b.y);
        mma8(acc0[g], a0, b0, b1);
        mma8(acc1[g], a1, b0, b1);
    }
}

// ---------------- CIN + aux kernel: 1 warp = 1 batch, CTA = 8 batches ----------------
// smem (floats): s_x 8*32*44=11264 | s_h1 8*32*68=17408 | ring 2*4096=8192 | s_cin 8*192=1536
__global__ __launch_bounds__(256, 1)
void cin_kernel(const float* __restrict__ x, const float* __restrict__ emb,
                const float* __restrict__ lin_w, const float* __restrict__ lin_b,
                const float* __restrict__ b0c, const float* __restrict__ b1c,
                const float* __restrict__ cow, const float* __restrict__ cob,
                float* __restrict__ out_aux) {
    extern __shared__ float sm[];
    float* s_x   = sm;                 // [b][d][44]
    float* s_h1  = sm + 11264;         // [b][d][68]
    float* s_w   = sm + 28672;         // ring: 2 x 4096
    float* s_cin = sm + 36864;         // [b][192]

    int tid = threadIdx.x;
    int lane = tid & 31;
    int w = tid >> 5;                  // warp = local batch
    int b0i = blockIdx.x * 8;

    // load emb [b][m][d] -> s_x [b][d][44] (transposed, coalesced reads)
    for (int idx = tid; idx < 10240; idx += 256) {
        int bb = idx / 1280;
        int r = idx - bb * 1280;
        int mm = r >> 5, dd = r & 31;
        s_x[bb * 1408 + dd * 44 + mm] = emb[(size_t)(b0i + bb) * 1280 + r];
    }
    __syncthreads();

    const float* s_xb = s_x + w * 1408;
    float* s_h1b = s_h1 + w * 2176;
    int q = lane >> 2, kc = lane & 3;

    float acc0[16][4], acc1[16][4];
#pragma unroll
    for (int g = 0; g < 16; g++)
#pragma unroll
        for (int i = 0; i < 4; i++) { acc0[g][i] = 0.0f; acc1[g][i] = 0.0f; }

    // ================= layer 0: 200 chunks (50 granules), K = 1600 =================
    issue_gran(s_w, g_w0P, tid);
    for (int gr = 0; gr < 50; gr++) {
        float* cur = s_w + (gr & 1) * 4096;
        if (gr + 1 < 50) { issue_gran(s_w + ((gr + 1) & 1) * 4096, g_w0P + (gr + 1) * 4096, tid); cpwait<1>(); }
        else cpwait<0>();
        __syncthreads();
#pragma unroll
        for (int cc = 0; cc < 4; cc++) {
            int c = gr * 4 + cc;
            int m = c / 5;
            int n0 = (c - m * 5) * 8;
            chunk_mma<44>(cur + cc * 1024, s_xb, s_xb, m, n0, lane, acc0, acc1);
        }
        __syncthreads();
    }

    // ---- epilogue 0: bias + relu; g<8 -> h1 (warp-local), g>=8 -> d-sum -> cin[0..63]
#pragma unroll
    for (int g = 0; g < 16; g++) {
        int o0 = g * 8 + 2 * kc;
        float bv0 = b0c[o0], bv1 = b0c[o0 + 1];
        float r00 = fmaxf(acc0[g][0] + bv0, 0.0f), r01 = fmaxf(acc0[g][1] + bv1, 0.0f);
        float r10 = fmaxf(acc0[g][2] + bv0, 0.0f), r11 = fmaxf(acc0[g][3] + bv1, 0.0f);
        float r20 = fmaxf(acc1[g][0] + bv0, 0.0f), r21 = fmaxf(acc1[g][1] + bv1, 0.0f);
        float r30 = fmaxf(acc1[g][2] + bv0, 0.0f), r31 = fmaxf(acc1[g][3] + bv1, 0.0f);
        if (g < 8) {
            *(float2*)(s_h1b + q * 68 + o0)        = make_float2(r00, r01);
            *(float2*)(s_h1b + (q + 8) * 68 + o0)  = make_float2(r10, r11);
            *(float2*)(s_h1b + (q + 16) * 68 + o0) = make_float2(r20, r21);
            *(float2*)(s_h1b + (q + 24) * 68 + o0) = make_float2(r30, r31);
        } else {
            float v0 = r00 + r10 + r20 + r30;
            float v1 = r01 + r11 + r21 + r31;
            v0 += __shfl_down_sync(0xffffffffu, v0, 16);
            v0 += __shfl_down_sync(0xffffffffu, v0, 8);
            v0 += __shfl_down_sync(0xffffffffu, v0, 4);
            v1 += __shfl_down_sync(0xffffffffu, v1, 16);
            v1 += __shfl_down_sync(0xffffffffu, v1, 8);
            v1 += __shfl_down_sync(0xffffffffu, v1, 4);
            if (lane < 4) {
                s_cin[w * 192 + o0 - 64] = v0;
                s_cin[w * 192 + o0 - 63] = v1;
            }
        }
    }
    __syncwarp();

#pragma unroll
    for (int g = 0; g < 16; g++)
#pragma unroll
        for (int i = 0; i < 4; i++) { acc0[g][i] = 0.0f; acc1[g][i] = 0.0f; }

    // ================= layer 1: 320 chunks (80 granules), K = 2560 =================
    issue_gran(s_w, g_w1P, tid);
    for (int gr = 0; gr < 80; gr++) {
        float* cur = s_w + (gr & 1) * 4096;
        if (gr + 1 < 80) { issue_gran(s_w + ((gr + 1) & 1) * 4096, g_w1P + (size_t)(gr + 1) * 4096, tid); cpwait<1>(); }
        else cpwait<0>();
        __syncthreads();
#pragma unroll
        for (int cc = 0; cc < 4; cc++) {
            int c = gr * 4 + cc;
            int m = c >> 3;
            int n0 = (c & 7) * 8;
            chunk_mma<68>(cur + cc * 1024, s_xb, s_h1b, m, n0, lane, acc0, acc1);
        }
        __syncthreads();
    }

    // ---- epilogue 1: bias + relu -> d-sum -> cin[64..191]
#pragma unroll
    for (int g = 0; g < 16; g++) {
        int o0 = g * 8 + 2 * kc;
        float bv0 = b1c[o0], bv1 = b1c[o0 + 1];
        float v0 = fmaxf(acc0[g][0] + bv0, 0.0f) + fmaxf(acc0[g][2] + bv0, 0.0f)
                 + fmaxf(acc1[g][0] + bv0, 0.0f) + fmaxf(acc1[g][2] + bv0, 0.0f);
        float v1 = fmaxf(acc0[g][1] + bv1, 0.0f) + fmaxf(acc0[g][3] + bv1, 0.0f)
                 + fmaxf(acc1[g][1] + bv1, 0.0f) + fmaxf(acc1[g][3] + bv1, 0.0f);
        v0 += __shfl_down_sync(0xffffffffu, v0, 16);
        v0 += __shfl_down_sync(0xffffffffu, v0, 8);
        v0 += __shfl_down_sync(0xffffffffu, v0, 4);
        v1 += __shfl_down_sync(0xffffffffu, v1, 16);
        v1 += __shfl_down_sync(0xffffffffu, v1, 8);
        v1 += __shfl_down_sync(0xffffffffu, v1, 4);
        if (lane < 4) {
            s_cin[w * 192 + 64 + o0] = v0;
            s_cin[w * 192 + 64 + o0 + 1] = v1;
        }
    }
    __syncwarp();

    // ================= aux: x . lin_w + cin_feat . cin_out_w (fp32 exact) =================
    {
        const float* xr = x + (size_t)(b0i + w) * 1280;
        float v = 0.0f;
#pragma unroll 8
        for (int t = 0; t < 40; t++) v += xr[lane + 32 * t] * lin_w[lane + 32 * t];
#pragma unroll
        for (int t = 0; t < 6; t++) v += s_cin[w * 192 + lane + 32 * t] * cow[lane + 32 * t];
#pragma unroll
        for (int off = 16; off > 0; off >>= 1)
            v += __shfl_down_sync(0xffffffffu, v, off);
        if (lane == 0) out_aux[b0i + w] = v + lin_b[0] + cob[0];
    }
}

// ---------------- deep tower: C = relu(LN(A @ W^T + b)), CTA = 64 rows (unchanged, proven) ----------------
template<int N>
__global__ __launch_bounds__(256, 2)
void deep_kernel(const float* __restrict__ A, int K,
                 const float* __restrict__ W, const float* __restrict__ bias,
                 const float* __restrict__ gam, const float* __restrict__ bet,
                 float* __restrict__ out) {
    constexpr int CPT = N / 32;
    __shared__ float sA[16][64];
    __shared__ float sW[16][N];
    int tid = threadIdx.x;
    int ty = tid >> 5, tx = tid & 31;
    int row0 = blockIdx.x * 64;

    float acc[8][CPT];
#pragma unroll
    for (int qq = 0; qq < 8; qq++)
#pragma unroll
        for (int p = 0; p < CPT; p++) acc[qq][p] = 0.0f;

    for (int kt = 0; kt < K; kt += 16) {
        {
            int r = tid >> 2, c = tid & 3;
            float4 a = *(const float4*)(A + (size_t)(row0 + r) * K + kt + c * 4);
            sA[c * 4 + 0][r] = a.x; sA[c * 4 + 1][r] = a.y;
            sA[c * 4 + 2][r] = a.z; sA[c * 4 + 3][r] = a.w;
        }
#pragma unroll
        for (int t = 0; t < N / 64; t++) {
            int v = tid + 256 * t;
            int n = v >> 2, c = v & 3;
            float4 ww = *(const float4*)(W + (size_t)n * K + kt + c * 4);
            sW[c * 4 + 0][n] = ww.x; sW[c * 4 + 1][n] = ww.y;
            sW[c * 4 + 2][n] = ww.z; sW[c * 4 + 3][n] = ww.w;
        }
        __syncthreads();
#pragma unroll
        for (int k = 0; k < 16; k++) {
            float ra[8], rw[CPT];
#pragma unroll
            for (int qq = 0; qq < 8; qq++) ra[qq] = sA[k][ty * 8 + qq];
#pragma unroll
            for (int p = 0; p < CPT; p++) rw[p] = sW[k][tx * CPT + p];
#pragma unroll
            for (int qq = 0; qq < 8; qq++)
#pragma unroll
                for (int p = 0; p < CPT; p++) acc[qq][p] += ra[qq] * rw[p];
        }
        __syncthreads();
    }

    float g[CPT], be[CPT], bv[CPT];
#pragma unroll
    for (int p = 0; p < CPT; p++) {
        g[p] = gam[tx * CPT + p]; be[p] = bet[tx * CPT + p]; bv[p] = bias[tx * CPT + p];
    }
#pragma unroll
    for (int qq = 0; qq < 8; qq++) {
#pragma unroll
        for (int p = 0; p < CPT; p++) acc[qq][p] += bv[p];
        float s = 0.0f;
#pragma unroll
        for (int p = 0; p < CPT; p++) s += acc[qq][p];
#pragma unroll
        for (int off = 16; off > 0; off >>= 1) s += __shfl_xor_sync(0xffffffffu, s, off);
        float mu = s * (1.0f / N);
        float vs = 0.0f;
#pragma unroll
        for (int p = 0; p < CPT; p++) { float d = acc[qq][p] - mu; vs += d * d; }
#pragma unroll
        for (int off = 16; off > 0; off >>= 1) vs += __shfl_xor_sync(0xffffffffu, vs, off);
        float rstd = rsqrtf(vs * (1.0f / N) + 1e-5f);
        size_t row = row0 + ty * 8 + qq;
#pragma unroll
        for (int p = 0; p < CPT; p++) {
            float val = (acc[qq][p] - mu) * rstd * g[p] + be[p];
            out[row * N + tx * CPT + p] = fmaxf(val, 0.0f);
        }
    }
}

// ---------------- launcher ----------------
extern "C" void kernel_launch(void* const* d_in, const int* in_sizes, int n_in,
                              void* d_out, int out_size) {
    const float* x     = (const float*)d_in[0];
    const float* emb   = (const float*)d_in[1];
    const float* lin_w = (const float*)d_in[2];
    const float* lin_b = (const float*)d_in[3];
    const float* w0    = (const float*)d_in[4];
    const float* b0c   = (const float*)d_in[5];
    const float* w1    = (const float*)d_in[6];
    const float* b1c   = (const float*)d_in[7];
    const float* cow   = (const float*)d_in[8];
    const float* cob   = (const float*)d_in[9];
    const float* dw0   = (const float*)d_in[10];
    const float* db0   = (const float*)d_in[11];
    const float* g0    = (const float*)d_in[12];
    const float* be0   = (const float*)d_in[13];
    const float* dw1   = (const float*)d_in[14];
    const float* db1   = (const float*)d_in[15];
    const float* g1    = (const float*)d_in[16];
    const float* be1   = (const float*)d_in[17];
    const float* dw2   = (const float*)d_in[18];
    const float* db2   = (const float*)d_in[19];
    const float* g2    = (const float*)d_in[20];
    const float* be2   = (const float*)d_in[21];

    float* out = (float*)d_out;
    float* h_out = out;                      // [B,64]
    float* aux_out = out + 16384 * 64;       // [B]

    void* h0p = nullptr; void* h1p = nullptr;
    cudaGetSymbolAddress(&h0p, g_h0);
    cudaGetSymbolAddress(&h1p, g_h1);

    static const int CIN_SMEM = 38408 * 4;   // ~150KB
    cudaFuncSetAttribute(cin_kernel, cudaFuncAttributeMaxDynamicSharedMemorySize, CIN_SMEM);

    prep_kernel<<<256, 256>>>(w0, w1);
    cin_kernel<<<2048, 256, CIN_SMEM>>>(x, emb, lin_w, lin_b, b0c, b1c, cow, cob, aux_out);
    deep_kernel<256><<<256, 256>>>(x, 1280, dw0, db0, g0, be0, (float*)h0p);
    deep_kernel<128><<<256, 256>>>((const float*)h0p, 256, dw1, db1, g1, be1, (float*)h1p);
    deep_kernel<64><<<256, 256>>>((const float*)h1p, 128, dw2, db2, g2, be2, h_out);
}